// round 15
// baseline (speedup 1.0000x reference)
#include <cuda_runtime.h>
#include <cuda_fp16.h>
#include <math.h>
#include <stdint.h>

#define DEV_INLINE __device__ __forceinline__

// Problem dims
constexpr int Bc = 2;
constexpr int Lc = 2048;
constexpr int Dc = 1024;
constexpr int Hc = 16;
constexpr int HDc = 64;
constexpr int Mc = Bc * Lc;      // 4096 rows
constexpr int DFc = 4096;        // FFN hidden

// -------- scratch (static device globals; no allocation at runtime) --------
__device__ __half g_xnh  [Mc * Dc];
__device__ __half g_yqkv [(size_t)Mc * 3 * Dc];
__device__ __half g_qh  [Mc * Dc];
__device__ __half g_kh  [Mc * Dc];
__device__ __half g_vh  [Mc * Dc];
__device__ __half g_vth [Mc * Dc];      // V transposed: [bh][hd][L]
__device__ float  g_k2  [Bc * Hc * Lc];
__device__ __half g_atth[Mc * Dc];
__device__ float  g_o   [Mc * Dc];
__device__ float  g_x2  [Mc * Dc];
__device__ __half g_ffhh[(size_t)Mc * DFc];
__device__ float  g_f2  [Mc * Dc];
// fp16 weights (qkv concatenated) + concat bias
__device__ __half g_hwqkv[(size_t)3 * Dc * Dc];
__device__ __half g_hwo[Dc * Dc];
__device__ __half g_hw1[(size_t)DFc * Dc];
__device__ __half g_hw2[(size_t)Dc * DFc];
__device__ float  g_bqkv[3 * Dc];

DEV_INLINE float warp_sum(float v) {
    #pragma unroll
    for (int o = 16; o > 0; o >>= 1) v += __shfl_xor_sync(0xffffffffu, v, o);
    return v;
}

DEV_INLINE void mma_f16(float* c, const uint32_t* a, const uint32_t* b) {
    asm volatile(
        "mma.sync.aligned.m16n8k16.row.col.f32.f16.f16.f32 "
        "{%0,%1,%2,%3}, {%4,%5,%6,%7}, {%8,%9}, {%0,%1,%2,%3};\n"
        : "+f"(c[0]), "+f"(c[1]), "+f"(c[2]), "+f"(c[3])
        : "r"(a[0]), "r"(a[1]), "r"(a[2]), "r"(a[3]),
          "r"(b[0]), "r"(b[1]));
}

DEV_INLINE uint32_t smem_u32(const void* p) {
    uint32_t a;
    asm("{ .reg .u64 t; cvta.to.shared.u64 t, %1; cvt.u32.u64 %0, t; }"
        : "=r"(a) : "l"(p));
    return a;
}

DEV_INLINE void cp16(uint32_t dst, const void* src) {
    asm volatile("cp.async.cg.shared.global [%0], [%1], 16;" :: "r"(dst), "l"(src));
}
#define CP_COMMIT() asm volatile("cp.async.commit_group;" ::: "memory")
template<int N> DEV_INLINE void cp_wait() {
    asm volatile("cp.async.wait_group %0;" :: "n"(N) : "memory");
}

// ---------------- single-launch weight rounding (all 6 matrices) ----------
constexpr int SEG_DD = (Dc * Dc) / 4;
constexpr int SEG_F  = ((int)((size_t)DFc * Dc)) / 4;
constexpr int ROUND_TOTAL = 4 * SEG_DD + 2 * SEG_F;

__global__ void round_all_kernel(const float* __restrict__ wq,
                                 const float* __restrict__ wk,
                                 const float* __restrict__ wv,
                                 const float* __restrict__ wo,
                                 const float* __restrict__ w1,
                                 const float* __restrict__ w2,
                                 __half* __restrict__ hwqkv,
                                 __half* __restrict__ hwo,
                                 __half* __restrict__ hw1,
                                 __half* __restrict__ hw2)
{
    int i = blockIdx.x * blockDim.x + threadIdx.x;
    if (i >= ROUND_TOTAL) return;
    const float* src;
    __half* dst;
    int off;
    if (i < SEG_DD)            { src = wq; dst = hwqkv;                          off = i; }
    else if (i < 2 * SEG_DD)   { src = wk; dst = hwqkv + (size_t)Dc * Dc;        off = i - SEG_DD; }
    else if (i < 3 * SEG_DD)   { src = wv; dst = hwqkv + (size_t)2 * Dc * Dc;    off = i - 2 * SEG_DD; }
    else if (i < 4 * SEG_DD)   { src = wo; dst = hwo;                            off = i - 3 * SEG_DD; }
    else if (i < 4 * SEG_DD + SEG_F) { src = w1; dst = hw1;                      off = i - 4 * SEG_DD; }
    else                       { src = w2; dst = hw2;                            off = i - 4 * SEG_DD - SEG_F; }
    float4 v = ((const float4*)src)[off];
    __half2 h0 = __floats2half2_rn(v.x, v.y);
    __half2 h1 = __floats2half2_rn(v.z, v.w);
    ((uint2*)dst)[off] = make_uint2(*(uint32_t*)&h0, *(uint32_t*)&h1);
}

__global__ void bias_cat_kernel(const float* __restrict__ a,
                                const float* __restrict__ b,
                                const float* __restrict__ c,
                                float* __restrict__ dst)
{
    int i = threadIdx.x + blockIdx.x * 256;
    if (i < Dc) { dst[i] = a[i]; dst[Dc + i] = b[i]; dst[2 * Dc + i] = c[i]; }
}

// ---------------- LayerNorm (emits fp16 output) ---------------------------
__global__ void ln_kernel(const float* __restrict__ x,
                          const float* __restrict__ g,
                          const float* __restrict__ b,
                          __half* __restrict__ y)
{
    __shared__ float red[8];
    int row = blockIdx.x;
    int t = threadIdx.x;
    const float4* xr = (const float4*)(x + (size_t)row * Dc);
    float4 v = xr[t];

    float s = v.x + v.y + v.z + v.w;
    s = warp_sum(s);
    if ((t & 31) == 0) red[t >> 5] = s;
    __syncthreads();
    float tot = 0.f;
    #pragma unroll
    for (int i = 0; i < 8; i++) tot += red[i];
    float mean = tot * (1.0f / Dc);
    __syncthreads();

    float dx = v.x - mean, dy = v.y - mean, dz = v.z - mean, dw = v.w - mean;
    float s2 = dx*dx + dy*dy + dz*dz + dw*dw;
    s2 = warp_sum(s2);
    if ((t & 31) == 0) red[t >> 5] = s2;
    __syncthreads();
    float tot2 = 0.f;
    #pragma unroll
    for (int i = 0; i < 8; i++) tot2 += red[i];
    float rstd = rsqrtf(tot2 * (1.0f / Dc) + 1e-5f);

    float4 gg = ((const float4*)g)[t];
    float4 bb = ((const float4*)b)[t];
    __half2 h0 = __floats2half2_rn(dx * rstd * gg.x + bb.x, dy * rstd * gg.y + bb.y);
    __half2 h1 = __floats2half2_rn(dz * rstd * gg.z + bb.z, dw * rstd * gg.w + bb.w);
    ((uint2*)(y + (size_t)row * Dc))[t] = make_uint2(*(uint32_t*)&h0, *(uint32_t*)&h1);
}

// ---------------- residual + Poincare projection (float out) -------------
__global__ void resproj_kernel(const float* __restrict__ x,
                               const float* __restrict__ add,
                               float* __restrict__ out)
{
    __shared__ float red[8];
    int row = blockIdx.x;
    int t = threadIdx.x;
    float4 a = ((const float4*)(x   + (size_t)row * Dc))[t];
    float4 c = ((const float4*)(add + (size_t)row * Dc))[t];
    float4 v = make_float4(a.x + c.x, a.y + c.y, a.z + c.z, a.w + c.w);

    float s = v.x*v.x + v.y*v.y + v.z*v.z + v.w*v.w;
    s = warp_sum(s);
    if ((t & 31) == 0) red[t >> 5] = s;
    __syncthreads();
    float tot = 0.f;
    #pragma unroll
    for (int i = 0; i < 8; i++) tot += red[i];
    float n = sqrtf(tot);
    const float maxn = 1.0f - 1e-5f;
    float sc = (n > maxn) ? (maxn / n) : 1.0f;

    v.x *= sc; v.y *= sc; v.z *= sc; v.w *= sc;
    ((float4*)(out + (size_t)row * Dc))[t] = v;
}

// ---------------- fused residual + projection + LayerNorm ----------------
__global__ void resproj_ln_kernel(const float* __restrict__ x,
                                  const float* __restrict__ add,
                                  const float* __restrict__ g,
                                  const float* __restrict__ b,
                                  float* __restrict__ x2,
                                  __half* __restrict__ xn)
{
    __shared__ float red[8];
    int row = blockIdx.x;
    int t = threadIdx.x;
    float4 a = ((const float4*)(x   + (size_t)row * Dc))[t];
    float4 c = ((const float4*)(add + (size_t)row * Dc))[t];
    float4 v = make_float4(a.x + c.x, a.y + c.y, a.z + c.z, a.w + c.w);

    float s = v.x*v.x + v.y*v.y + v.z*v.z + v.w*v.w;
    s = warp_sum(s);
    if ((t & 31) == 0) red[t >> 5] = s;
    __syncthreads();
    float tot = 0.f;
    #pragma unroll
    for (int i = 0; i < 8; i++) tot += red[i];
    float n = sqrtf(tot);
    const float maxn = 1.0f - 1e-5f;
    float sc = (n > maxn) ? (maxn / n) : 1.0f;
    v.x *= sc; v.y *= sc; v.z *= sc; v.w *= sc;
    ((float4*)(x2 + (size_t)row * Dc))[t] = v;
    __syncthreads();

    float sm = v.x + v.y + v.z + v.w;
    sm = warp_sum(sm);
    if ((t & 31) == 0) red[t >> 5] = sm;
    __syncthreads();
    float tm = 0.f;
    #pragma unroll
    for (int i = 0; i < 8; i++) tm += red[i];
    float mean = tm * (1.0f / Dc);
    __syncthreads();

    float dx = v.x - mean, dy = v.y - mean, dz = v.z - mean, dw = v.w - mean;
    float s2 = dx*dx + dy*dy + dz*dz + dw*dw;
    s2 = warp_sum(s2);
    if ((t & 31) == 0) red[t >> 5] = s2;
    __syncthreads();
    float t2 = 0.f;
    #pragma unroll
    for (int i = 0; i < 8; i++) t2 += red[i];
    float rstd = rsqrtf(t2 * (1.0f / Dc) + 1e-5f);

    float4 gg = ((const float4*)g)[t];
    float4 bb = ((const float4*)b)[t];
    __half2 h0 = __floats2half2_rn(dx * rstd * gg.x + bb.x, dy * rstd * gg.y + bb.y);
    __half2 h1 = __floats2half2_rn(dz * rstd * gg.z + bb.z, dw * rstd * gg.w + bb.w);
    ((uint2*)(xn + (size_t)row * Dc))[t] = make_uint2(*(uint32_t*)&h0, *(uint32_t*)&h1);
}

// ---------------- fp16 GEMM: BK=64, 3-stage, single-sync multistage -------
// Row = 64 halves padded to 72 (stride 36 words) — the conflict-free pattern
// proven in the attention kernel. One __syncthreads per K-chunk of 64.
constexpr int RW64   = 36;                 // words per 64-half row
constexpr int MATW64 = 128 * RW64;         // 4608 words per matrix per stage
constexpr int STW64  = 2 * MATW64;         // A+B per stage (words)
constexpr int NSTG   = 3;
constexpr int G_SMEM = NSTG * STW64 * 4;   // 110592 bytes

template<int EPI>
__global__ __launch_bounds__(256, 2)
void gemm_fp16(const __half* __restrict__ A, const __half* __restrict__ B,
               const float* __restrict__ bias, void* __restrict__ Cv,
               int M, int N, int K)
{
    extern __shared__ uint32_t sh[];
    uint32_t shb = smem_u32(sh);

    int tid = threadIdx.x;
    int bm = blockIdx.y * 128, bn = blockIdx.x * 128;
    int lane = tid & 31, warp = tid >> 5;
    int wm = (warp & 3) * 32;
    int wn = (warp >> 2) * 64;
    int grp = lane >> 2, kq = lane & 3;

    float acc[2][8][4];
    #pragma unroll
    for (int mt = 0; mt < 2; mt++)
        #pragma unroll
        for (int nt = 0; nt < 8; nt++)
            #pragma unroll
            for (int r = 0; r < 4; r++) acc[mt][nt][r] = 0.f;

    // fill mapping: 2 threads per row, 32 halves (4 cp16) each per matrix
    int lrow = tid >> 1;
    int fch  = (tid & 1) * 32;
    const __half* Ap = A + (size_t)(bm + lrow) * K + fch;
    const __half* Bp = B + (size_t)(bn + lrow) * K + fch;
    uint32_t sA = shb + (uint32_t)(lrow * 72 + fch) * 2;
    uint32_t sB = sA + MATW64 * 4;

    const int nk = K / 64;

    auto issue = [&](int stage, int k0) {
        uint32_t d = (uint32_t)stage * STW64 * 4;
        const __half* as = Ap + k0;
        const __half* bs = Bp + k0;
        #pragma unroll
        for (int j = 0; j < 4; j++) {
            cp16(sA + d + j * 16, as + j * 8);
            cp16(sB + d + j * 16, bs + j * 8);
        }
        CP_COMMIT();
    };

    issue(0, 0);
    if (nk > 1) issue(1, 64);

    for (int it = 0; it < nk; it++) {
        if (it + 1 < nk) cp_wait<1>(); else cp_wait<0>();
        __syncthreads();
        if (it + 2 < nk) issue((it + 2) % NSTG, (it + 2) * 64);

        const uint32_t* As = sh + (it % NSTG) * STW64;
        const uint32_t* Bs = As + MATW64;

        #pragma unroll
        for (int ks = 0; ks < 4; ks++) {
            int kb = ks * 8 + kq;
            uint32_t a[2][4], b[8][2];
            #pragma unroll
            for (int mt = 0; mt < 2; mt++) {
                int m = wm + mt * 16 + grp;
                a[mt][0] = As[(m    ) * RW64 + kb];
                a[mt][1] = As[(m + 8) * RW64 + kb];
                a[mt][2] = As[(m    ) * RW64 + kb + 4];
                a[mt][3] = As[(m + 8) * RW64 + kb + 4];
            }
            #pragma unroll
            for (int nt = 0; nt < 8; nt++) {
                int n = wn + nt * 8 + grp;
                b[nt][0] = Bs[n * RW64 + kb];
                b[nt][1] = Bs[n * RW64 + kb + 4];
            }
            #pragma unroll
            for (int mt = 0; mt < 2; mt++)
                #pragma unroll
                for (int nt = 0; nt < 8; nt++)
                    mma_f16(acc[mt][nt], a[mt], b[nt]);
        }
        // no bottom sync: next iteration's top sync guards stage reuse
    }

    #pragma unroll
    for (int mt = 0; mt < 2; mt++) {
        int row0 = bm + wm + mt * 16 + grp;
        #pragma unroll
        for (int nt = 0; nt < 8; nt++) {
            int col = bn + wn + nt * 8 + kq * 2;
            float b0 = bias[col], b1 = bias[col + 1];
            float v0 = acc[mt][nt][0] + b0;
            float v1 = acc[mt][nt][1] + b1;
            float v2 = acc[mt][nt][2] + b0;
            float v3 = acc[mt][nt][3] + b1;
            if (EPI == 1) {
                v0 = 0.5f * v0 * (1.0f + erff(v0 * 0.70710678118654752f));
                v1 = 0.5f * v1 * (1.0f + erff(v1 * 0.70710678118654752f));
                v2 = 0.5f * v2 * (1.0f + erff(v2 * 0.70710678118654752f));
                v3 = 0.5f * v3 * (1.0f + erff(v3 * 0.70710678118654752f));
            }
            if (EPI >= 1) {
                __half* C = (__half*)Cv;
                *(__half2*)(C + (size_t)row0 * N + col)       = __floats2half2_rn(v0, v1);
                *(__half2*)(C + (size_t)(row0 + 8) * N + col) = __floats2half2_rn(v2, v3);
            } else {
                float* C = (float*)Cv;
                *(float2*)(C + (size_t)row0 * N + col)       = make_float2(v0, v1);
                *(float2*)(C + (size_t)(row0 + 8) * N + col) = make_float2(v2, v3);
            }
        }
    }
}

// ---------------- head split + projection; reads fp16 fused yqkv ----------
__global__ void qkv_tr_kernel(const __half* __restrict__ yqkv,
                              __half* __restrict__ q, __half* __restrict__ k,
                              __half* __restrict__ v, float* __restrict__ k2)
{
    int bl = blockIdx.x;
    int b = bl >> 11;
    int l = bl & 2047;
    int w = threadIdx.x >> 5;
    int lane = threadIdx.x & 31;
    const float maxn = 1.0f - 1e-5f;

    size_t base = (size_t)bl * (3 * Dc) + w * HDc + lane * 2;
    size_t dst  = ((size_t)(b * Hc + w) * Lc + l) * HDc + lane * 2;

    float2 qv = __half22float2(*(const __half2*)(yqkv + base));
    float sq = warp_sum(qv.x*qv.x + qv.y*qv.y);
    float nq = sqrtf(sq);
    float scq = ((nq > maxn) ? (maxn / nq) : 1.0f) * 0.25f;
    *(__half2*)(q + dst) = __floats2half2_rn(qv.x * scq, qv.y * scq);

    float2 kv = __half22float2(*(const __half2*)(yqkv + base + Dc));
    float sk = warp_sum(kv.x*kv.x + kv.y*kv.y);
    float nk = sqrtf(sk);
    float sck = (nk > maxn) ? (maxn / nk) : 1.0f;
    *(__half2*)(k + dst) = __floats2half2_rn(kv.x * sck, kv.y * sck);
    if (lane == 0) k2[(size_t)(b * Hc + w) * Lc + l] = sk * sck * sck * 0.125f;

    *(__half2*)(v + dst) = *(const __half2*)(yqkv + base + 2 * Dc);
}

// ---------------- V transpose: [bh][l][hd] -> [bh][hd][l] -----------------
__global__ void v_tr_kernel(const __half* __restrict__ v,
                            __half* __restrict__ vt)
{
    __shared__ __half sm[64 * 72];
    int bh = blockIdx.x, lt = blockIdx.y;
    int tid = threadIdx.x;

    const __half* src = v + ((size_t)bh * Lc + lt * 64) * HDc;
    #pragma unroll
    for (int i = 0; i < 2; i++) {
        int gid = tid + i * 256;
        int r = gid >> 3, c = (gid & 7) * 8;
        *(uint4*)&sm[r * 72 + c] = *(const uint4*)(src + r * HDc + c);
    }
    __syncthreads();

    __half* dst = vt + ((size_t)bh * HDc) * Lc + lt * 64;
    #pragma unroll
    for (int i = 0; i < 2; i++) {
        int gid = tid + i * 256;
        int hd = gid >> 3, ls = (gid & 7) * 8;
        __half tmp[8];
        #pragma unroll
        for (int j = 0; j < 8; j++) tmp[j] = sm[(ls + j) * 72 + hd];
        *(uint4*)(dst + (size_t)hd * Lc + ls) = *(uint4*)tmp;
    }
}

// ---------------- flash attention, fp16 mma, 3-stage single-sync KV -------
constexpr int AW = 36;
constexpr int KVSTG = 2 * 64 * AW;           // K+VT words per stage
constexpr int A_NSTG = 3;
constexpr int ATT_SMEM = (128 * AW + A_NSTG * KVSTG) * 4 + A_NSTG * 64 * 4;

__global__ __launch_bounds__(256, 2)
void attn_mma_kernel(const __half* __restrict__ q, const __half* __restrict__ k,
                     const __half* __restrict__ vt, const float* __restrict__ k2,
                     __half* __restrict__ out)
{
    extern __shared__ uint32_t usm[];
    uint32_t* Qs  = usm;
    uint32_t* KV  = Qs + 128 * AW;
    float* k2s    = (float*)(KV + A_NSTG * KVSTG);
    uint32_t shb  = smem_u32(usm);
    uint32_t kvb  = shb + 128 * AW * 4;
    uint32_t k2b  = kvb + A_NSTG * KVSTG * 4;

    int qb = blockIdx.x, bh = blockIdx.y;
    int tid = threadIdx.x, lane = tid & 31, warp = tid >> 5;
    int wm = warp * 16, grp = lane >> 2, kq = lane & 3;

    const __half* qbase = q + ((size_t)bh * Lc + qb * 128) * HDc;
    #pragma unroll
    for (int it = 0; it < 4; it++) {
        int id = tid + it * 256;
        int r = id >> 3, cw = (id & 7) * 4;
        *(uint4*)&Qs[r * AW + cw] = *(const uint4*)(qbase + r * HDc + cw * 2);
    }

    const __half* kbase  = k  + (size_t)bh * Lc * HDc;
    const __half* vtbase = vt + (size_t)bh * HDc * Lc;
    const float*  k2base = k2 + (size_t)bh * Lc;
    int frow = tid >> 2;
    int fcw  = (tid & 3) * 8;
    auto issue_kv = [&](int stage, int jb) {
        uint32_t ks = kvb + (uint32_t)stage * KVSTG * 4;
        uint32_t vs = ks + 64 * AW * 4;
        const __half* kp = kbase + (size_t)jb * 64 * HDc;
        const __half* vp = vtbase + (size_t)jb * 64;
        uint32_t kd = ks + (uint32_t)(frow * AW + fcw) * 4;
        uint32_t vd = vs + (uint32_t)(frow * AW + fcw) * 4;
        cp16(kd,      kp + frow * HDc + fcw * 2);
        cp16(kd + 16, kp + frow * HDc + fcw * 2 + 8);
        cp16(vd,      vp + (size_t)frow * Lc + fcw * 2);
        cp16(vd + 16, vp + (size_t)frow * Lc + fcw * 2 + 8);
        if (tid < 16)
            cp16(k2b + (uint32_t)(stage * 64 + tid * 4) * 4,
                 k2base + (size_t)jb * 64 + tid * 4);
        CP_COMMIT();
    };

    issue_kv(0, 0);
    issue_kv(1, 1);
    __syncthreads();   // Qs visible

    uint32_t qf[4][4];
    #pragma unroll
    for (int ks = 0; ks < 4; ks++) {
        int kb = ks * 8 + kq, m = wm + grp;
        qf[ks][0] = Qs[m * AW + kb];
        qf[ks][1] = Qs[(m + 8) * AW + kb];
        qf[ks][2] = Qs[m * AW + kb + 4];
        qf[ks][3] = Qs[(m + 8) * AW + kb + 4];
    }

    float o[8][4];
    #pragma unroll
    for (int nt = 0; nt < 8; nt++)
        #pragma unroll
        for (int r = 0; r < 4; r++) o[nt][r] = 0.f;
    float m0 = -INFINITY, m1 = -INFINITY, l0 = 0.f, l1 = 0.f;

    const int NJB = Lc / 64;
    for (int jb = 0; jb < NJB; jb++) {
        if (jb + 1 < NJB) cp_wait<1>(); else cp_wait<0>();
        __syncthreads();
        if (jb + 2 < NJB) issue_kv((jb + 2) % A_NSTG, jb + 2);

        int st = jb % A_NSTG;
        const uint32_t* Ks = KV + st * KVSTG;
        const uint32_t* Vs = Ks + 64 * AW;
        const float* k2c = k2s + st * 64;

        float s[8][4];
        #pragma unroll
        for (int nt = 0; nt < 8; nt++)
            #pragma unroll
            for (int r = 0; r < 4; r++) s[nt][r] = 0.f;

        #pragma unroll
        for (int ks = 0; ks < 4; ks++) {
            int kb = ks * 8 + kq;
            uint32_t b[8][2];
            #pragma unroll
            for (int nt = 0; nt < 8; nt++) {
                int n = nt * 8 + grp;
                b[nt][0] = Ks[n * AW + kb];
                b[nt][1] = Ks[n * AW + kb + 4];
            }
            #pragma unroll
            for (int nt = 0; nt < 8; nt++)
                mma_f16(s[nt], qf[ks], b[nt]);
        }

        #pragma unroll
        for (int nt = 0; nt < 8; nt++) {
            float ka  = k2c[nt * 8 + kq * 2];
            float kbv = k2c[nt * 8 + kq * 2 + 1];
            s[nt][0] -= ka; s[nt][1] -= kbv;
            s[nt][2] -= ka; s[nt][3] -= kbv;
        }

        float rm0 = -INFINITY, rm1 = -INFINITY;
        #pragma unroll
        for (int nt = 0; nt < 8; nt++) {
            rm0 = fmaxf(rm0, fmaxf(s[nt][0], s[nt][1]));
            rm1 = fmaxf(rm1, fmaxf(s[nt][2], s[nt][3]));
        }
        #pragma unroll
        for (int ofs = 1; ofs < 4; ofs <<= 1) {
            rm0 = fmaxf(rm0, __shfl_xor_sync(0xffffffffu, rm0, ofs));
            rm1 = fmaxf(rm1, __shfl_xor_sync(0xffffffffu, rm1, ofs));
        }
        float mn0 = fmaxf(m0, rm0), mn1 = fmaxf(m1, rm1);
        float al0 = __expf(m0 - mn0), al1 = __expf(m1 - mn1);
        float rs0 = 0.f, rs1 = 0.f;

        uint32_t* Ps = Qs;
        int prow = (wm + grp) * AW + kq;
        #pragma unroll
        for (int nt = 0; nt < 8; nt++) {
            float p0 = __expf(s[nt][0] - mn0);
            float p1 = __expf(s[nt][1] - mn0);
            float p2 = __expf(s[nt][2] - mn1);
            float p3 = __expf(s[nt][3] - mn1);
            rs0 += p0 + p1; rs1 += p2 + p3;
            __half2 hlo = __floats2half2_rn(p0, p1);
            __half2 hhi = __floats2half2_rn(p2, p3);
            Ps[prow + nt * 4]          = *(uint32_t*)&hlo;
            Ps[prow + 8 * AW + nt * 4] = *(uint32_t*)&hhi;
        }
        #pragma unroll
        for (int ofs = 1; ofs < 4; ofs <<= 1) {
            rs0 += __shfl_xor_sync(0xffffffffu, rs0, ofs);
            rs1 += __shfl_xor_sync(0xffffffffu, rs1, ofs);
        }
        l0 = l0 * al0 + rs0; m0 = mn0;
        l1 = l1 * al1 + rs1; m1 = mn1;
        #pragma unroll
        for (int nt = 0; nt < 8; nt++) {
            o[nt][0] *= al0; o[nt][1] *= al0;
            o[nt][2] *= al1; o[nt][3] *= al1;
        }
        __syncwarp();

        #pragma unroll
        for (int ks = 0; ks < 4; ks++) {
            int kb = ks * 8 + kq, m = wm + grp;
            uint32_t a[4];
            a[0] = Ps[m * AW + kb];
            a[1] = Ps[(m + 8) * AW + kb];
            a[2] = Ps[m * AW + kb + 4];
            a[3] = Ps[(m + 8) * AW + kb + 4];
            uint32_t b[8][2];
            #pragma unroll
            for (int nt = 0; nt < 8; nt++) {
                int n = nt * 8 + grp;
                b[nt][0] = Vs[n * AW + kb];
                b[nt][1] = Vs[n * AW + kb + 4];
            }
            #pragma unroll
            for (int nt = 0; nt < 8; nt++)
                mma_f16(o[nt], a, b[nt]);
        }
        // no bottom sync: next iteration's top sync guards stage reuse
    }

    float inv0 = 1.0f / l0, inv1 = 1.0f / l1;
    int b_ = bh >> 4, h = bh & 15;
    int row0 = qb * 128 + wm + grp;
    #pragma unroll
    for (int nt = 0; nt < 8; nt++) {
        int col = h * HDc + nt * 8 + kq * 2;
        *(__half2*)(out + ((size_t)(b_ * Lc + row0)) * Dc + col) =
            __floats2half2_rn(o[nt][0] * inv0, o[nt][1] * inv0);
        *(__half2*)(out + ((size_t)(b_ * Lc + row0 + 8)) * Dc + col) =
            __floats2half2_rn(o[nt][2] * inv1, o[nt][3] * inv1);
    }
}

// -------------------------------- host ----------------------------------
static void* sym_ptr_raw(const void* sym) {
    void* p = nullptr;
    cudaGetSymbolAddress(&p, sym);
    return p;
}

extern "C" void kernel_launch(void* const* d_in, const int* in_sizes, int n_in,
                              void* d_out, int out_size)
{
    const float* x   = (const float*)d_in[0];
    const float* wq  = (const float*)d_in[1];
    const float* bq  = (const float*)d_in[2];
    const float* wk  = (const float*)d_in[3];
    const float* bk  = (const float*)d_in[4];
    const float* wv  = (const float*)d_in[5];
    const float* bv  = (const float*)d_in[6];
    const float* wo  = (const float*)d_in[7];
    const float* bo  = (const float*)d_in[8];
    const float* g1  = (const float*)d_in[9];
    const float* b1  = (const float*)d_in[10];
    const float* g2  = (const float*)d_in[11];
    const float* b2  = (const float*)d_in[12];
    const float* w1  = (const float*)d_in[13];
    const float* bf1 = (const float*)d_in[14];
    const float* w2  = (const float*)d_in[15];
    const float* bf2 = (const float*)d_in[16];
    float* out = (float*)d_out;

    __half* xnh   = (__half*)sym_ptr_raw(g_xnh);
    __half* yqkv  = (__half*)sym_ptr_raw(g_yqkv);
    __half* qh    = (__half*)sym_ptr_raw(g_qh);
    __half* kh    = (__half*)sym_ptr_raw(g_kh);
    __half* vh    = (__half*)sym_ptr_raw(g_vh);
    __half* vth   = (__half*)sym_ptr_raw(g_vth);
    float*  k2d   = (float*)sym_ptr_raw(g_k2);
    __half* atth  = (__half*)sym_ptr_raw(g_atth);
    float*  od    = (float*)sym_ptr_raw(g_o);
    float*  x2    = (float*)sym_ptr_raw(g_x2);
    __half* ffhh  = (__half*)sym_ptr_raw(g_ffhh);
    float*  f2    = (float*)sym_ptr_raw(g_f2);
    __half* hwqkv = (__half*)sym_ptr_raw(g_hwqkv);
    __half* hwo   = (__half*)sym_ptr_raw(g_hwo);
    __half* hw1   = (__half*)sym_ptr_raw(g_hw1);
    __half* hw2   = (__half*)sym_ptr_raw(g_hw2);
    float*  bqkv  = (float*)sym_ptr_raw(g_bqkv);

    cudaFuncSetAttribute(gemm_fp16<0>, cudaFuncAttributeMaxDynamicSharedMemorySize, G_SMEM);
    cudaFuncSetAttribute(gemm_fp16<1>, cudaFuncAttributeMaxDynamicSharedMemorySize, G_SMEM);
    cudaFuncSetAttribute(gemm_fp16<2>, cudaFuncAttributeMaxDynamicSharedMemorySize, G_SMEM);
    cudaFuncSetAttribute(attn_mma_kernel, cudaFuncAttributeMaxDynamicSharedMemorySize, ATT_SMEM);

    round_all_kernel<<<(ROUND_TOTAL + 255) / 256, 256>>>(
        wq, wk, wv, wo, w1, w2, hwqkv, hwo, hw1, hw2);
    bias_cat_kernel<<<(Dc + 255) / 256, 256>>>(bq, bk, bv, bqkv);

    dim3 gQkv(3 * Dc / 128, Mc / 128);  // (24, 32)
    dim3 gProj(Dc / 128, Mc / 128);     // (8, 32)
    dim3 gFfn1(DFc / 128, Mc / 128);    // (32, 32)

    ln_kernel<<<Mc, 256>>>(x, g1, b1, xnh);
    gemm_fp16<2><<<gQkv, 256, G_SMEM>>>(xnh, hwqkv, bqkv, yqkv, Mc, 3 * Dc, Dc);
    qkv_tr_kernel<<<Mc, 512>>>(yqkv, qh, kh, vh, k2d);
    v_tr_kernel<<<dim3(Bc * Hc, Lc / 64), 256>>>(vh, vth);

    attn_mma_kernel<<<dim3(Lc / 128, Bc * Hc), 256, ATT_SMEM>>>(qh, kh, vth, k2d, atth);

    gemm_fp16<0><<<gProj, 256, G_SMEM>>>(atth, hwo, bo, od, Mc, Dc, Dc);
    resproj_ln_kernel<<<Mc, 256>>>(x, od, g2, b2, x2, xnh);
    gemm_fp16<1><<<gFfn1, 256, G_SMEM>>>(xnh, hw1, bf1, ffhh, Mc, DFc, Dc);
    gemm_fp16<0><<<gProj, 256, G_SMEM>>>(ffhh, hw2, bf2, f2, Mc, Dc, DFc);
    resproj_kernel<<<Mc, 256>>>(x2, f2, out);
}

// round 16
// speedup vs baseline: 1.0354x; 1.0354x over previous
#include <cuda_runtime.h>
#include <cuda_fp16.h>
#include <math.h>
#include <stdint.h>

#define DEV_INLINE __device__ __forceinline__

// Problem dims
constexpr int Bc = 2;
constexpr int Lc = 2048;
constexpr int Dc = 1024;
constexpr int Hc = 16;
constexpr int HDc = 64;
constexpr int Mc = Bc * Lc;      // 4096 rows
constexpr int DFc = 4096;        // FFN hidden

// -------- scratch (static device globals; no allocation at runtime) --------
__device__ __half g_xnh  [Mc * Dc];
__device__ __half g_yqkv [(size_t)Mc * 3 * Dc];
__device__ __half g_qh  [Mc * Dc];
__device__ __half g_kh  [Mc * Dc];
__device__ __half g_vh  [Mc * Dc];
__device__ __half g_vth [Mc * Dc];      // V transposed: [bh][hd][L]
__device__ float  g_k2  [Bc * Hc * Lc];
__device__ __half g_atth[Mc * Dc];
__device__ __half g_oh  [Mc * Dc];
__device__ float  g_x2  [Mc * Dc];
__device__ __half g_ffhh[(size_t)Mc * DFc];
__device__ __half g_f2h [Mc * Dc];
// fp16 weights (qkv concatenated) + concat bias
__device__ __half g_hwqkv[(size_t)3 * Dc * Dc];
__device__ __half g_hwo[Dc * Dc];
__device__ __half g_hw1[(size_t)DFc * Dc];
__device__ __half g_hw2[(size_t)Dc * DFc];
__device__ float  g_bqkv[3 * Dc];

DEV_INLINE float warp_sum(float v) {
    #pragma unroll
    for (int o = 16; o > 0; o >>= 1) v += __shfl_xor_sync(0xffffffffu, v, o);
    return v;
}

DEV_INLINE void mma_f16(float* c, const uint32_t* a, const uint32_t* b) {
    asm volatile(
        "mma.sync.aligned.m16n8k16.row.col.f32.f16.f16.f32 "
        "{%0,%1,%2,%3}, {%4,%5,%6,%7}, {%8,%9}, {%0,%1,%2,%3};\n"
        : "+f"(c[0]), "+f"(c[1]), "+f"(c[2]), "+f"(c[3])
        : "r"(a[0]), "r"(a[1]), "r"(a[2]), "r"(a[3]),
          "r"(b[0]), "r"(b[1]));
}

DEV_INLINE uint32_t smem_u32(const void* p) {
    uint32_t a;
    asm("{ .reg .u64 t; cvta.to.shared.u64 t, %1; cvt.u32.u64 %0, t; }"
        : "=r"(a) : "l"(p));
    return a;
}

DEV_INLINE void cp16(uint32_t dst, const void* src) {
    asm volatile("cp.async.cg.shared.global [%0], [%1], 16;" :: "r"(dst), "l"(src));
}
#define CP_COMMIT() asm volatile("cp.async.commit_group;" ::: "memory")
template<int N> DEV_INLINE void cp_wait() {
    asm volatile("cp.async.wait_group %0;" :: "n"(N) : "memory");
}

// ---------------- single-launch weight rounding (all 6 matrices) ----------
constexpr int SEG_DD = (Dc * Dc) / 4;
constexpr int SEG_F  = ((int)((size_t)DFc * Dc)) / 4;
constexpr int ROUND_TOTAL = 4 * SEG_DD + 2 * SEG_F;

__global__ void round_all_kernel(const float* __restrict__ wq,
                                 const float* __restrict__ wk,
                                 const float* __restrict__ wv,
                                 const float* __restrict__ wo,
                                 const float* __restrict__ w1,
                                 const float* __restrict__ w2,
                                 __half* __restrict__ hwqkv,
                                 __half* __restrict__ hwo,
                                 __half* __restrict__ hw1,
                                 __half* __restrict__ hw2)
{
    int i = blockIdx.x * blockDim.x + threadIdx.x;
    if (i >= ROUND_TOTAL) return;
    const float* src;
    __half* dst;
    int off;
    if (i < SEG_DD)            { src = wq; dst = hwqkv;                          off = i; }
    else if (i < 2 * SEG_DD)   { src = wk; dst = hwqkv + (size_t)Dc * Dc;        off = i - SEG_DD; }
    else if (i < 3 * SEG_DD)   { src = wv; dst = hwqkv + (size_t)2 * Dc * Dc;    off = i - 2 * SEG_DD; }
    else if (i < 4 * SEG_DD)   { src = wo; dst = hwo;                            off = i - 3 * SEG_DD; }
    else if (i < 4 * SEG_DD + SEG_F) { src = w1; dst = hw1;                      off = i - 4 * SEG_DD; }
    else                       { src = w2; dst = hw2;                            off = i - 4 * SEG_DD - SEG_F; }
    float4 v = ((const float4*)src)[off];
    __half2 h0 = __floats2half2_rn(v.x, v.y);
    __half2 h1 = __floats2half2_rn(v.z, v.w);
    ((uint2*)dst)[off] = make_uint2(*(uint32_t*)&h0, *(uint32_t*)&h1);
}

__global__ void bias_cat_kernel(const float* __restrict__ a,
                                const float* __restrict__ b,
                                const float* __restrict__ c,
                                float* __restrict__ dst)
{
    int i = threadIdx.x + blockIdx.x * 256;
    if (i < Dc) { dst[i] = a[i]; dst[Dc + i] = b[i]; dst[2 * Dc + i] = c[i]; }
}

// ---------------- LayerNorm (emits fp16 output) ---------------------------
__global__ void ln_kernel(const float* __restrict__ x,
                          const float* __restrict__ g,
                          const float* __restrict__ b,
                          __half* __restrict__ y)
{
    __shared__ float red[8];
    int row = blockIdx.x;
    int t = threadIdx.x;
    const float4* xr = (const float4*)(x + (size_t)row * Dc);
    float4 v = xr[t];

    float s = v.x + v.y + v.z + v.w;
    s = warp_sum(s);
    if ((t & 31) == 0) red[t >> 5] = s;
    __syncthreads();
    float tot = 0.f;
    #pragma unroll
    for (int i = 0; i < 8; i++) tot += red[i];
    float mean = tot * (1.0f / Dc);
    __syncthreads();

    float dx = v.x - mean, dy = v.y - mean, dz = v.z - mean, dw = v.w - mean;
    float s2 = dx*dx + dy*dy + dz*dz + dw*dw;
    s2 = warp_sum(s2);
    if ((t & 31) == 0) red[t >> 5] = s2;
    __syncthreads();
    float tot2 = 0.f;
    #pragma unroll
    for (int i = 0; i < 8; i++) tot2 += red[i];
    float rstd = rsqrtf(tot2 * (1.0f / Dc) + 1e-5f);

    float4 gg = ((const float4*)g)[t];
    float4 bb = ((const float4*)b)[t];
    __half2 h0 = __floats2half2_rn(dx * rstd * gg.x + bb.x, dy * rstd * gg.y + bb.y);
    __half2 h1 = __floats2half2_rn(dz * rstd * gg.z + bb.z, dw * rstd * gg.w + bb.w);
    ((uint2*)(y + (size_t)row * Dc))[t] = make_uint2(*(uint32_t*)&h0, *(uint32_t*)&h1);
}

// ---------------- residual(f32 + fp16) + Poincare projection -> f32 ------
__global__ void resproj_h_kernel(const float* __restrict__ x,
                                 const __half* __restrict__ add,
                                 float* __restrict__ out)
{
    __shared__ float red[8];
    int row = blockIdx.x;
    int t = threadIdx.x;
    float4 a = ((const float4*)(x + (size_t)row * Dc))[t];
    uint2 hraw = ((const uint2*)(add + (size_t)row * Dc))[t];
    float2 c0 = __half22float2(*(__half2*)&hraw.x);
    float2 c1 = __half22float2(*(__half2*)&hraw.y);
    float4 v = make_float4(a.x + c0.x, a.y + c0.y, a.z + c1.x, a.w + c1.y);

    float s = v.x*v.x + v.y*v.y + v.z*v.z + v.w*v.w;
    s = warp_sum(s);
    if ((t & 31) == 0) red[t >> 5] = s;
    __syncthreads();
    float tot = 0.f;
    #pragma unroll
    for (int i = 0; i < 8; i++) tot += red[i];
    float n = sqrtf(tot);
    const float maxn = 1.0f - 1e-5f;
    float sc = (n > maxn) ? (maxn / n) : 1.0f;

    v.x *= sc; v.y *= sc; v.z *= sc; v.w *= sc;
    ((float4*)(out + (size_t)row * Dc))[t] = v;
}

// ---------------- fused residual(f32+fp16) + projection + LayerNorm ------
__global__ void resproj_ln_kernel(const float* __restrict__ x,
                                  const __half* __restrict__ add,
                                  const float* __restrict__ g,
                                  const float* __restrict__ b,
                                  float* __restrict__ x2,
                                  __half* __restrict__ xn)
{
    __shared__ float red[8];
    int row = blockIdx.x;
    int t = threadIdx.x;
    float4 a = ((const float4*)(x + (size_t)row * Dc))[t];
    uint2 hraw = ((const uint2*)(add + (size_t)row * Dc))[t];
    float2 c0 = __half22float2(*(__half2*)&hraw.x);
    float2 c1 = __half22float2(*(__half2*)&hraw.y);
    float4 v = make_float4(a.x + c0.x, a.y + c0.y, a.z + c1.x, a.w + c1.y);

    float s = v.x*v.x + v.y*v.y + v.z*v.z + v.w*v.w;
    s = warp_sum(s);
    if ((t & 31) == 0) red[t >> 5] = s;
    __syncthreads();
    float tot = 0.f;
    #pragma unroll
    for (int i = 0; i < 8; i++) tot += red[i];
    float n = sqrtf(tot);
    const float maxn = 1.0f - 1e-5f;
    float sc = (n > maxn) ? (maxn / n) : 1.0f;
    v.x *= sc; v.y *= sc; v.z *= sc; v.w *= sc;
    ((float4*)(x2 + (size_t)row * Dc))[t] = v;
    __syncthreads();

    float sm = v.x + v.y + v.z + v.w;
    sm = warp_sum(sm);
    if ((t & 31) == 0) red[t >> 5] = sm;
    __syncthreads();
    float tm = 0.f;
    #pragma unroll
    for (int i = 0; i < 8; i++) tm += red[i];
    float mean = tm * (1.0f / Dc);
    __syncthreads();

    float dx = v.x - mean, dy = v.y - mean, dz = v.z - mean, dw = v.w - mean;
    float s2 = dx*dx + dy*dy + dz*dz + dw*dw;
    s2 = warp_sum(s2);
    if ((t & 31) == 0) red[t >> 5] = s2;
    __syncthreads();
    float t2 = 0.f;
    #pragma unroll
    for (int i = 0; i < 8; i++) t2 += red[i];
    float rstd = rsqrtf(t2 * (1.0f / Dc) + 1e-5f);

    float4 gg = ((const float4*)g)[t];
    float4 bb = ((const float4*)b)[t];
    __half2 h0 = __floats2half2_rn(dx * rstd * gg.x + bb.x, dy * rstd * gg.y + bb.y);
    __half2 h1 = __floats2half2_rn(dz * rstd * gg.z + bb.z, dw * rstd * gg.w + bb.w);
    ((uint2*)(xn + (size_t)row * Dc))[t] = make_uint2(*(uint32_t*)&h0, *(uint32_t*)&h1);
}

// ---------------- fp16 GEMM (exact R14 = best proven config) --------------
// EPI: 0 = f32 out, 1 = GELU + f16 out, 2 = bias-only f16 out
constexpr int LDH    = 40;               // halves per row
constexpr int MATW16 = 128 * LDH / 2;    // words per matrix (2560)
constexpr int STW16  = 2 * MATW16;       // A+B per stage (words)
constexpr int NSTG   = 3;
constexpr int G_SMEM = NSTG * STW16 * 4; // 61440 bytes

template<int EPI>
__global__ __launch_bounds__(256, 2)
void gemm_fp16(const __half* __restrict__ A, const __half* __restrict__ B,
               const float* __restrict__ bias, void* __restrict__ Cv,
               int M, int N, int K)
{
    extern __shared__ uint32_t sh[];
    uint32_t shb = smem_u32(sh);

    int tid = threadIdx.x;
    int bm = blockIdx.y * 128, bn = blockIdx.x * 128;
    int lane = tid & 31, warp = tid >> 5;
    int wm = (warp & 3) * 32;
    int wn = (warp >> 2) * 64;
    int grp = lane >> 2, kq = lane & 3;

    float acc[2][8][4];
    #pragma unroll
    for (int mt = 0; mt < 2; mt++)
        #pragma unroll
        for (int nt = 0; nt < 8; nt++)
            #pragma unroll
            for (int r = 0; r < 4; r++) acc[mt][nt][r] = 0.f;

    int lrow = tid >> 1;
    int fch  = (tid & 1) * 16;
    const __half* Ap = A + (size_t)(bm + lrow) * K + fch;
    const __half* Bp = B + (size_t)(bn + lrow) * K + fch;
    uint32_t sA = shb + (uint32_t)(lrow * LDH + fch) * 2;
    uint32_t sB = sA + MATW16 * 4;

    const int nk = K / 32;

    auto issue = [&](int stage, int k0) {
        uint32_t d = (uint32_t)stage * STW16 * 4;
        const __half* as = Ap + k0;
        const __half* bs = Bp + k0;
        cp16(sA + d,      as);
        cp16(sA + d + 16, as + 8);
        cp16(sB + d,      bs);
        cp16(sB + d + 16, bs + 8);
        CP_COMMIT();
    };

    issue(0, 0);
    if (nk > 1) issue(1, 32);
    if (nk > 2) issue(2, 64);

    for (int it = 0; it < nk; it++) {
        int rem = nk - 1 - it;
        if (rem >= 2) cp_wait<2>();
        else if (rem == 1) cp_wait<1>();
        else cp_wait<0>();
        __syncthreads();

        int st = it % NSTG;
        const uint32_t* As = sh + st * STW16;
        const uint32_t* Bs = As + MATW16;

        #pragma unroll
        for (int ks = 0; ks < 2; ks++) {
            int kb = ks * 8 + kq;
            uint32_t a[2][4], b[8][2];
            #pragma unroll
            for (int mt = 0; mt < 2; mt++) {
                int m = wm + mt * 16 + grp;
                a[mt][0] = As[(m    ) * 20 + kb];
                a[mt][1] = As[(m + 8) * 20 + kb];
                a[mt][2] = As[(m    ) * 20 + kb + 4];
                a[mt][3] = As[(m + 8) * 20 + kb + 4];
            }
            #pragma unroll
            for (int nt = 0; nt < 8; nt++) {
                int n = wn + nt * 8 + grp;
                b[nt][0] = Bs[n * 20 + kb];
                b[nt][1] = Bs[n * 20 + kb + 4];
            }
            #pragma unroll
            for (int mt = 0; mt < 2; mt++)
                #pragma unroll
                for (int nt = 0; nt < 8; nt++)
                    mma_f16(acc[mt][nt], a[mt], b[nt]);
        }
        __syncthreads();
        if (it + NSTG < nk) issue(st, (it + NSTG) * 32);
    }

    #pragma unroll
    for (int mt = 0; mt < 2; mt++) {
        int row0 = bm + wm + mt * 16 + grp;
        #pragma unroll
        for (int nt = 0; nt < 8; nt++) {
            int col = bn + wn + nt * 8 + kq * 2;
            float b0 = bias[col], b1 = bias[col + 1];
            float v0 = acc[mt][nt][0] + b0;
            float v1 = acc[mt][nt][1] + b1;
            float v2 = acc[mt][nt][2] + b0;
            float v3 = acc[mt][nt][3] + b1;
            if (EPI == 1) {
                v0 = 0.5f * v0 * (1.0f + erff(v0 * 0.70710678118654752f));
                v1 = 0.5f * v1 * (1.0f + erff(v1 * 0.70710678118654752f));
                v2 = 0.5f * v2 * (1.0f + erff(v2 * 0.70710678118654752f));
                v3 = 0.5f * v3 * (1.0f + erff(v3 * 0.70710678118654752f));
            }
            if (EPI >= 1) {
                __half* C = (__half*)Cv;
                *(__half2*)(C + (size_t)row0 * N + col)       = __floats2half2_rn(v0, v1);
                *(__half2*)(C + (size_t)(row0 + 8) * N + col) = __floats2half2_rn(v2, v3);
            } else {
                float* C = (float*)Cv;
                *(float2*)(C + (size_t)row0 * N + col)       = make_float2(v0, v1);
                *(float2*)(C + (size_t)(row0 + 8) * N + col) = make_float2(v2, v3);
            }
        }
    }
}

// ---------------- head split + projection; reads fp16 fused yqkv ----------
__global__ void qkv_tr_kernel(const __half* __restrict__ yqkv,
                              __half* __restrict__ q, __half* __restrict__ k,
                              __half* __restrict__ v, float* __restrict__ k2)
{
    int bl = blockIdx.x;
    int b = bl >> 11;
    int l = bl & 2047;
    int w = threadIdx.x >> 5;
    int lane = threadIdx.x & 31;
    const float maxn = 1.0f - 1e-5f;

    size_t base = (size_t)bl * (3 * Dc) + w * HDc + lane * 2;
    size_t dst  = ((size_t)(b * Hc + w) * Lc + l) * HDc + lane * 2;

    float2 qv = __half22float2(*(const __half2*)(yqkv + base));
    float sq = warp_sum(qv.x*qv.x + qv.y*qv.y);
    float nq = sqrtf(sq);
    float scq = ((nq > maxn) ? (maxn / nq) : 1.0f) * 0.25f;
    *(__half2*)(q + dst) = __floats2half2_rn(qv.x * scq, qv.y * scq);

    float2 kv = __half22float2(*(const __half2*)(yqkv + base + Dc));
    float sk = warp_sum(kv.x*kv.x + kv.y*kv.y);
    float nk = sqrtf(sk);
    float sck = (nk > maxn) ? (maxn / nk) : 1.0f;
    *(__half2*)(k + dst) = __floats2half2_rn(kv.x * sck, kv.y * sck);
    if (lane == 0) k2[(size_t)(b * Hc + w) * Lc + l] = sk * sck * sck * 0.125f;

    *(__half2*)(v + dst) = *(const __half2*)(yqkv + base + 2 * Dc);
}

// ---------------- V transpose: [bh][l][hd] -> [bh][hd][l] -----------------
__global__ void v_tr_kernel(const __half* __restrict__ v,
                            __half* __restrict__ vt)
{
    __shared__ __half sm[64 * 72];
    int bh = blockIdx.x, lt = blockIdx.y;
    int tid = threadIdx.x;

    const __half* src = v + ((size_t)bh * Lc + lt * 64) * HDc;
    #pragma unroll
    for (int i = 0; i < 2; i++) {
        int gid = tid + i * 256;
        int r = gid >> 3, c = (gid & 7) * 8;
        *(uint4*)&sm[r * 72 + c] = *(const uint4*)(src + r * HDc + c);
    }
    __syncthreads();

    __half* dst = vt + ((size_t)bh * HDc) * Lc + lt * 64;
    #pragma unroll
    for (int i = 0; i < 2; i++) {
        int gid = tid + i * 256;
        int hd = gid >> 3, ls = (gid & 7) * 8;
        __half tmp[8];
        #pragma unroll
        for (int j = 0; j < 8; j++) tmp[j] = sm[(ls + j) * 72 + hd];
        *(uint4*)(dst + (size_t)hd * Lc + ls) = *(uint4*)tmp;
    }
}

// ---------------- flash attention, full fp16 mma (exact R12-14, proven) ---
constexpr int AW = 36;
constexpr int KVSTG = 2 * 64 * AW;
constexpr int ATT_SMEM = (128 * AW + 2 * KVSTG) * 4 + 2 * 64 * 4;

__global__ __launch_bounds__(256, 2)
void attn_mma_kernel(const __half* __restrict__ q, const __half* __restrict__ k,
                     const __half* __restrict__ vt, const float* __restrict__ k2,
                     __half* __restrict__ out)
{
    extern __shared__ uint32_t usm[];
    uint32_t* Qs  = usm;
    uint32_t* KV  = Qs + 128 * AW;
    float* k2s    = (float*)(KV + 2 * KVSTG);
    uint32_t shb  = smem_u32(usm);
    uint32_t kvb  = shb + 128 * AW * 4;
    uint32_t k2b  = kvb + 2 * KVSTG * 4;

    int qb = blockIdx.x, bh = blockIdx.y;
    int tid = threadIdx.x, lane = tid & 31, warp = tid >> 5;
    int wm = warp * 16, grp = lane >> 2, kq = lane & 3;

    const __half* qbase = q + ((size_t)bh * Lc + qb * 128) * HDc;
    #pragma unroll
    for (int it = 0; it < 4; it++) {
        int id = tid + it * 256;
        int r = id >> 3, cw = (id & 7) * 4;
        *(uint4*)&Qs[r * AW + cw] = *(const uint4*)(qbase + r * HDc + cw * 2);
    }

    const __half* kbase  = k  + (size_t)bh * Lc * HDc;
    const __half* vtbase = vt + (size_t)bh * HDc * Lc;
    const float*  k2base = k2 + (size_t)bh * Lc;
    int frow = tid >> 2;
    int fcw  = (tid & 3) * 8;
    auto issue_kv = [&](int stage, int jb) {
        uint32_t ks = kvb + (uint32_t)stage * KVSTG * 4;
        uint32_t vs = ks + 64 * AW * 4;
        const __half* kp = kbase + (size_t)jb * 64 * HDc;
        const __half* vp = vtbase + (size_t)jb * 64;
        uint32_t kd = ks + (uint32_t)(frow * AW + fcw) * 4;
        uint32_t vd = vs + (uint32_t)(frow * AW + fcw) * 4;
        cp16(kd,      kp + frow * HDc + fcw * 2);
        cp16(kd + 16, kp + frow * HDc + fcw * 2 + 8);
        cp16(vd,      vp + (size_t)frow * Lc + fcw * 2);
        cp16(vd + 16, vp + (size_t)frow * Lc + fcw * 2 + 8);
        if (tid < 16)
            cp16(k2b + (uint32_t)(stage * 64 + tid * 4) * 4,
                 k2base + (size_t)jb * 64 + tid * 4);
        CP_COMMIT();
    };

    issue_kv(0, 0);
    issue_kv(1, 1);
    __syncthreads();

    uint32_t qf[4][4];
    #pragma unroll
    for (int ks = 0; ks < 4; ks++) {
        int kb = ks * 8 + kq, m = wm + grp;
        qf[ks][0] = Qs[m * AW + kb];
        qf[ks][1] = Qs[(m + 8) * AW + kb];
        qf[ks][2] = Qs[m * AW + kb + 4];
        qf[ks][3] = Qs[(m + 8) * AW + kb + 4];
    }

    float o[8][4];
    #pragma unroll
    for (int nt = 0; nt < 8; nt++)
        #pragma unroll
        for (int r = 0; r < 4; r++) o[nt][r] = 0.f;
    float m0 = -INFINITY, m1 = -INFINITY, l0 = 0.f, l1 = 0.f;

    const int NJB = Lc / 64;
    for (int jb = 0; jb < NJB; jb++) {
        if (jb + 1 < NJB) cp_wait<1>(); else cp_wait<0>();
        __syncthreads();

        int st = jb & 1;
        const uint32_t* Ks = KV + st * KVSTG;
        const uint32_t* Vs = Ks + 64 * AW;
        const float* k2c = k2s + st * 64;

        float s[8][4];
        #pragma unroll
        for (int nt = 0; nt < 8; nt++)
            #pragma unroll
            for (int r = 0; r < 4; r++) s[nt][r] = 0.f;

        #pragma unroll
        for (int ks = 0; ks < 4; ks++) {
            int kb = ks * 8 + kq;
            uint32_t b[8][2];
            #pragma unroll
            for (int nt = 0; nt < 8; nt++) {
                int n = nt * 8 + grp;
                b[nt][0] = Ks[n * AW + kb];
                b[nt][1] = Ks[n * AW + kb + 4];
            }
            #pragma unroll
            for (int nt = 0; nt < 8; nt++)
                mma_f16(s[nt], qf[ks], b[nt]);
        }

        #pragma unroll
        for (int nt = 0; nt < 8; nt++) {
            float ka  = k2c[nt * 8 + kq * 2];
            float kbv = k2c[nt * 8 + kq * 2 + 1];
            s[nt][0] -= ka; s[nt][1] -= kbv;
            s[nt][2] -= ka; s[nt][3] -= kbv;
        }

        float rm0 = -INFINITY, rm1 = -INFINITY;
        #pragma unroll
        for (int nt = 0; nt < 8; nt++) {
            rm0 = fmaxf(rm0, fmaxf(s[nt][0], s[nt][1]));
            rm1 = fmaxf(rm1, fmaxf(s[nt][2], s[nt][3]));
        }
        #pragma unroll
        for (int ofs = 1; ofs < 4; ofs <<= 1) {
            rm0 = fmaxf(rm0, __shfl_xor_sync(0xffffffffu, rm0, ofs));
            rm1 = fmaxf(rm1, __shfl_xor_sync(0xffffffffu, rm1, ofs));
        }
        float mn0 = fmaxf(m0, rm0), mn1 = fmaxf(m1, rm1);
        float al0 = __expf(m0 - mn0), al1 = __expf(m1 - mn1);
        float rs0 = 0.f, rs1 = 0.f;

        uint32_t* Ps = Qs;
        int prow = (wm + grp) * AW + kq;
        #pragma unroll
        for (int nt = 0; nt < 8; nt++) {
            float p0 = __expf(s[nt][0] - mn0);
            float p1 = __expf(s[nt][1] - mn0);
            float p2 = __expf(s[nt][2] - mn1);
            float p3 = __expf(s[nt][3] - mn1);
            rs0 += p0 + p1; rs1 += p2 + p3;
            __half2 hlo = __floats2half2_rn(p0, p1);
            __half2 hhi = __floats2half2_rn(p2, p3);
            Ps[prow + nt * 4]          = *(uint32_t*)&hlo;
            Ps[prow + 8 * AW + nt * 4] = *(uint32_t*)&hhi;
        }
        #pragma unroll
        for (int ofs = 1; ofs < 4; ofs <<= 1) {
            rs0 += __shfl_xor_sync(0xffffffffu, rs0, ofs);
            rs1 += __shfl_xor_sync(0xffffffffu, rs1, ofs);
        }
        l0 = l0 * al0 + rs0; m0 = mn0;
        l1 = l1 * al1 + rs1; m1 = mn1;
        #pragma unroll
        for (int nt = 0; nt < 8; nt++) {
            o[nt][0] *= al0; o[nt][1] *= al0;
            o[nt][2] *= al1; o[nt][3] *= al1;
        }
        __syncwarp();

        #pragma unroll
        for (int ks = 0; ks < 4; ks++) {
            int kb = ks * 8 + kq, m = wm + grp;
            uint32_t a[4];
            a[0] = Ps[m * AW + kb];
            a[1] = Ps[(m + 8) * AW + kb];
            a[2] = Ps[m * AW + kb + 4];
            a[3] = Ps[(m + 8) * AW + kb + 4];
            uint32_t b[8][2];
            #pragma unroll
            for (int nt = 0; nt < 8; nt++) {
                int n = nt * 8 + grp;
                b[nt][0] = Vs[n * AW + kb];
                b[nt][1] = Vs[n * AW + kb + 4];
            }
            #pragma unroll
            for (int nt = 0; nt < 8; nt++)
                mma_f16(o[nt], a, b[nt]);
        }
        __syncthreads();
        if (jb + 2 < NJB) issue_kv(st, jb + 2);
    }

    float inv0 = 1.0f / l0, inv1 = 1.0f / l1;
    int b_ = bh >> 4, h = bh & 15;
    int row0 = qb * 128 + wm + grp;
    #pragma unroll
    for (int nt = 0; nt < 8; nt++) {
        int col = h * HDc + nt * 8 + kq * 2;
        *(__half2*)(out + ((size_t)(b_ * Lc + row0)) * Dc + col) =
            __floats2half2_rn(o[nt][0] * inv0, o[nt][1] * inv0);
        *(__half2*)(out + ((size_t)(b_ * Lc + row0 + 8)) * Dc + col) =
            __floats2half2_rn(o[nt][2] * inv1, o[nt][3] * inv1);
    }
}

// -------------------------------- host ----------------------------------
static void* sym_ptr_raw(const void* sym) {
    void* p = nullptr;
    cudaGetSymbolAddress(&p, sym);
    return p;
}

extern "C" void kernel_launch(void* const* d_in, const int* in_sizes, int n_in,
                              void* d_out, int out_size)
{
    const float* x   = (const float*)d_in[0];
    const float* wq  = (const float*)d_in[1];
    const float* bq  = (const float*)d_in[2];
    const float* wk  = (const float*)d_in[3];
    const float* bk  = (const float*)d_in[4];
    const float* wv  = (const float*)d_in[5];
    const float* bv  = (const float*)d_in[6];
    const float* wo  = (const float*)d_in[7];
    const float* bo  = (const float*)d_in[8];
    const float* g1  = (const float*)d_in[9];
    const float* b1  = (const float*)d_in[10];
    const float* g2  = (const float*)d_in[11];
    const float* b2  = (const float*)d_in[12];
    const float* w1  = (const float*)d_in[13];
    const float* bf1 = (const float*)d_in[14];
    const float* w2  = (const float*)d_in[15];
    const float* bf2 = (const float*)d_in[16];
    float* out = (float*)d_out;

    __half* xnh   = (__half*)sym_ptr_raw(g_xnh);
    __half* yqkv  = (__half*)sym_ptr_raw(g_yqkv);
    __half* qh    = (__half*)sym_ptr_raw(g_qh);
    __half* kh    = (__half*)sym_ptr_raw(g_kh);
    __half* vh    = (__half*)sym_ptr_raw(g_vh);
    __half* vth   = (__half*)sym_ptr_raw(g_vth);
    float*  k2d   = (float*)sym_ptr_raw(g_k2);
    __half* atth  = (__half*)sym_ptr_raw(g_atth);
    __half* oh    = (__half*)sym_ptr_raw(g_oh);
    float*  x2    = (float*)sym_ptr_raw(g_x2);
    __half* ffhh  = (__half*)sym_ptr_raw(g_ffhh);
    __half* f2h   = (__half*)sym_ptr_raw(g_f2h);
    __half* hwqkv = (__half*)sym_ptr_raw(g_hwqkv);
    __half* hwo   = (__half*)sym_ptr_raw(g_hwo);
    __half* hw1   = (__half*)sym_ptr_raw(g_hw1);
    __half* hw2   = (__half*)sym_ptr_raw(g_hw2);
    float*  bqkv  = (float*)sym_ptr_raw(g_bqkv);

    cudaFuncSetAttribute(gemm_fp16<1>, cudaFuncAttributeMaxDynamicSharedMemorySize, G_SMEM);
    cudaFuncSetAttribute(gemm_fp16<2>, cudaFuncAttributeMaxDynamicSharedMemorySize, G_SMEM);
    cudaFuncSetAttribute(attn_mma_kernel, cudaFuncAttributeMaxDynamicSharedMemorySize, ATT_SMEM);

    round_all_kernel<<<(ROUND_TOTAL + 255) / 256, 256>>>(
        wq, wk, wv, wo, w1, w2, hwqkv, hwo, hw1, hw2);
    bias_cat_kernel<<<(Dc + 255) / 256, 256>>>(bq, bk, bv, bqkv);

    dim3 gQkv(3 * Dc / 128, Mc / 128);  // (24, 32)
    dim3 gProj(Dc / 128, Mc / 128);     // (8, 32)
    dim3 gFfn1(DFc / 128, Mc / 128);    // (32, 32)

    ln_kernel<<<Mc, 256>>>(x, g1, b1, xnh);
    gemm_fp16<2><<<gQkv, 256, G_SMEM>>>(xnh, hwqkv, bqkv, yqkv, Mc, 3 * Dc, Dc);
    qkv_tr_kernel<<<Mc, 512>>>(yqkv, qh, kh, vh, k2d);
    v_tr_kernel<<<dim3(Bc * Hc, Lc / 64), 256>>>(vh, vth);

    attn_mma_kernel<<<dim3(Lc / 128, Bc * Hc), 256, ATT_SMEM>>>(qh, kh, vth, k2d, atth);

    gemm_fp16<2><<<gProj, 256, G_SMEM>>>(atth, hwo, bo, oh, Mc, Dc, Dc);
    resproj_ln_kernel<<<Mc, 256>>>(x, oh, g2, b2, x2, xnh);
    gemm_fp16<1><<<gFfn1, 256, G_SMEM>>>(xnh, hw1, bf1, ffhh, Mc, DFc, Dc);
    gemm_fp16<2><<<gProj, 256, G_SMEM>>>(ffhh, hw2, bf2, f2h, Mc, Dc, DFc);
    resproj_h_kernel<<<Mc, 256>>>(x2, f2h, out);
}